// round 7
// baseline (speedup 1.0000x reference)
#include <cuda_runtime.h>
#include <cstdint>

// ---------------- problem constants ----------------
#define MAXN 100000
#define MAXE 3200000
#define NG   64

// ---------------- device scratch (static, referenced ONLY from device code) ----
__device__ int   g_deg[MAXN];
__device__ float g_dinv[MAXN];
__device__ int   g_colptr[MAXN + 1];
__device__ int   g_cursor[MAXN];
__device__ int2  g_edge[MAXE];            // (src, float bits of norm)
__device__ float g_agg1[(size_t)MAXN * 128];
__device__ float g_h1  [(size_t)MAXN * 256];
__device__ float g_agg2[(size_t)MAXN * 256];
__device__ float g_h2  [(size_t)MAXN * 256];
__device__ float g_sums[NG * 256];
__device__ float g_cnt [NG];

// ---------------- prep kernels ----------------
__global__ void init_kernel(int n) {
    int i = blockIdx.x * blockDim.x + threadIdx.x;
    if (i < n) g_deg[i] = 0;
    if (i < NG * 256) g_sums[i] = 0.f;
    if (i < NG) g_cnt[i] = 0.f;
}

__global__ void deg_kernel(const int* __restrict__ ei, int E, int n) {
    int e = blockIdx.x * blockDim.x + threadIdx.x;
    if (e < E) {
        unsigned c = (unsigned)ei[E + e];
        if (c < (unsigned)n) atomicAdd(&g_deg[c], 1);
    }
}

__global__ void dinv_kernel(int n) {
    int i = blockIdx.x * blockDim.x + threadIdx.x;
    if (i < n) g_dinv[i] = rsqrtf((float)(g_deg[i] + 1));   // +1 self loop
}

// single-block exclusive scan over g_deg -> g_colptr / g_cursor
__global__ void scan_kernel(int n) {
    __shared__ int wsum[32];
    __shared__ int carry_sh;
    int lane = threadIdx.x & 31, wid = threadIdx.x >> 5;
    if (threadIdx.x == 0) carry_sh = 0;
    __syncthreads();
    for (int base = 0; base < n; base += 1024) {
        int i = base + threadIdx.x;
        int v = (i < n) ? g_deg[i] : 0;
        int s = v;
        #pragma unroll
        for (int off = 1; off < 32; off <<= 1) {
            int t = __shfl_up_sync(0xffffffffu, s, off);
            if (lane >= off) s += t;
        }
        if (lane == 31) wsum[wid] = s;
        __syncthreads();
        if (wid == 0) {
            int t = wsum[lane];
            int ss = t;
            #pragma unroll
            for (int off = 1; off < 32; off <<= 1) {
                int u = __shfl_up_sync(0xffffffffu, ss, off);
                if (lane >= off) ss += u;
            }
            wsum[lane] = ss - t;   // exclusive warp offsets
        }
        __syncthreads();
        int excl = carry_sh + wsum[wid] + s - v;
        if (i < n) { g_colptr[i] = excl; g_cursor[i] = excl; }
        __syncthreads();
        if (threadIdx.x == 1023) carry_sh += wsum[31] + s;   // chunk total
        __syncthreads();
    }
    if (threadIdx.x == 0) g_colptr[n] = carry_sh;
}

__global__ void fill_kernel(const int* __restrict__ ei, int E, int n) {
    int e = blockIdx.x * blockDim.x + threadIdx.x;
    if (e >= E) return;
    unsigned r = (unsigned)ei[e];
    unsigned c = (unsigned)ei[E + e];
    if (r >= (unsigned)n || c >= (unsigned)n) return;
    int p = atomicAdd(&g_cursor[c], 1);
    g_edge[p] = make_int2((int)r, __float_as_int(g_dinv[r] * g_dinv[c]));
}

// ---------------- aggregation (CSR gather, no fp atomics) ----------------
// layer 1, D=128: warp per node, lane owns one float4. X = harness input x.
__global__ void agg_d128(const float4* __restrict__ X, int n) {
    int node = blockIdx.x * 8 + (threadIdx.x >> 5);
    if (node >= n) return;
    int lane = threadIdx.x & 31;
    float di = g_dinv[node];
    float self = di * di;
    float4 xv = X[(size_t)node * 32 + lane];
    float4 acc = make_float4(xv.x * self, xv.y * self, xv.z * self, xv.w * self);
    int s = g_colptr[node], e = g_colptr[node + 1];
    for (int p = s; p < e; p++) {
        int2 ed = g_edge[p];
        float w = __int_as_float(ed.y);
        float4 v = X[(size_t)ed.x * 32 + lane];
        acc.x = fmaf(v.x, w, acc.x);
        acc.y = fmaf(v.y, w, acc.y);
        acc.z = fmaf(v.z, w, acc.z);
        acc.w = fmaf(v.w, w, acc.w);
    }
    ((float4*)g_agg1)[(size_t)node * 32 + lane] = acc;
}

// layer 2, D=256: warp per node, lane owns two float4s. Reads g_h1 -> writes g_agg2.
__global__ void agg_d256(int n) {
    int node = blockIdx.x * 8 + (threadIdx.x >> 5);
    if (node >= n) return;
    int lane = threadIdx.x & 31;
    const float4* X = (const float4*)g_h1;
    float di = g_dinv[node];
    float self = di * di;
    size_t base = (size_t)node * 64 + lane;
    float4 x0 = X[base], x1 = X[base + 32];
    float4 a0 = make_float4(x0.x * self, x0.y * self, x0.z * self, x0.w * self);
    float4 a1 = make_float4(x1.x * self, x1.y * self, x1.z * self, x1.w * self);
    int s = g_colptr[node], e = g_colptr[node + 1];
    for (int p = s; p < e; p++) {
        int2 ed = g_edge[p];
        float w = __int_as_float(ed.y);
        size_t rb = (size_t)ed.x * 64 + lane;
        float4 v0 = X[rb], v1 = X[rb + 32];
        a0.x = fmaf(v0.x, w, a0.x); a0.y = fmaf(v0.y, w, a0.y);
        a0.z = fmaf(v0.z, w, a0.z); a0.w = fmaf(v0.w, w, a0.w);
        a1.x = fmaf(v1.x, w, a1.x); a1.y = fmaf(v1.y, w, a1.y);
        a1.z = fmaf(v1.z, w, a1.z); a1.w = fmaf(v1.w, w, a1.w);
    }
    float4* O = (float4*)g_agg2;
    O[base] = a0;
    O[base + 32] = a1;
}

// ---------------- fused SGEMM + bias + relu: C[M,256] = A[M,K] @ B[K,256] ----------
// Scratch A/C are selected by template parameter; only harness pointers are args.
template<int LAYER>
__global__ __launch_bounds__(256, 2) void sgemm_bias_relu(
    const float* __restrict__ B, const float* __restrict__ bias, int M)
{
    constexpr int K = (LAYER == 1) ? 128 : 256;
    const int N = 256;
    const float* A = (LAYER == 1) ? g_agg1 : g_agg2;
    float*       C = (LAYER == 1) ? g_h1   : g_h2;

    __shared__ float As[8][128];
    __shared__ float Bs[8][128];
    int tid = threadIdx.x;
    int tx = tid & 15;        // 16 col-groups of 8
    int ty = tid >> 4;        // 16 row-groups of 8
    int row0 = blockIdx.y * 128;
    int col0 = blockIdx.x * 128;

    float acc[8][8];
    #pragma unroll
    for (int i = 0; i < 8; i++)
        #pragma unroll
        for (int j = 0; j < 8; j++) acc[i][j] = 0.f;

    int a_r = tid >> 1;            // 0..127
    int a_c = (tid & 1) * 4;       // 0 or 4
    int b_r = tid >> 5;            // 0..7
    int b_c = (tid & 31) * 4;      // 0..124

    bool a_ok = (row0 + a_r) < M;
    const float* Aptr = A + (size_t)(row0 + a_r) * K + a_c;
    const float* Bptr = B + (size_t)b_r * N + col0 + b_c;

    for (int k0 = 0; k0 < K; k0 += 8) {
        float4 av = make_float4(0.f, 0.f, 0.f, 0.f);
        if (a_ok) av = *(const float4*)(Aptr + k0);
        float4 bv = *(const float4*)(Bptr + (size_t)k0 * N);
        As[a_c + 0][a_r] = av.x;
        As[a_c + 1][a_r] = av.y;
        As[a_c + 2][a_r] = av.z;
        As[a_c + 3][a_r] = av.w;
        *(float4*)&Bs[b_r][b_c] = bv;
        __syncthreads();
        #pragma unroll
        for (int k = 0; k < 8; k++) {
            float ra[8], rb[8];
            *(float4*)&ra[0] = *(const float4*)&As[k][ty * 8];
            *(float4*)&ra[4] = *(const float4*)&As[k][ty * 8 + 4];
            *(float4*)&rb[0] = *(const float4*)&Bs[k][tx * 8];
            *(float4*)&rb[4] = *(const float4*)&Bs[k][tx * 8 + 4];
            #pragma unroll
            for (int i = 0; i < 8; i++)
                #pragma unroll
                for (int j = 0; j < 8; j++)
                    acc[i][j] = fmaf(ra[i], rb[j], acc[i][j]);
        }
        __syncthreads();
    }

    #pragma unroll
    for (int i = 0; i < 8; i++) {
        int r = row0 + ty * 8 + i;
        if (r >= M) continue;
        #pragma unroll
        for (int jj = 0; jj < 2; jj++) {
            int c = col0 + tx * 8 + jj * 4;
            float4 v;
            v.x = fmaxf(acc[i][jj * 4 + 0] + bias[c + 0], 0.f);
            v.y = fmaxf(acc[i][jj * 4 + 1] + bias[c + 1], 0.f);
            v.z = fmaxf(acc[i][jj * 4 + 2] + bias[c + 2], 0.f);
            v.w = fmaxf(acc[i][jj * 4 + 3] + bias[c + 3], 0.f);
            *(float4*)(C + (size_t)r * 256 + c) = v;
        }
    }
}

// ---------------- pooling ----------------
// block = 256 threads (one per column), handles 64 contiguous (sorted) nodes
__global__ void pool_kernel(const int* __restrict__ batch, int n) {
    int c = threadIdx.x;
    int start = blockIdx.x * 64;
    if (start >= n) return;
    int end = min(start + 64, n);
    float acc = 0.f;
    int g = batch[start] & (NG - 1);
    for (int i = start; i < end; i++) {
        int gi = batch[i] & (NG - 1);
        if (gi != g) {
            atomicAdd(&g_sums[g * 256 + c], acc);
            acc = 0.f;
            g = gi;
        }
        acc += g_h2[(size_t)i * 256 + c];
    }
    atomicAdd(&g_sums[g * 256 + c], acc);
}

__global__ void count_kernel(const int* __restrict__ batch, int n) {
    int i = blockIdx.x * blockDim.x + threadIdx.x;
    if (i < n) atomicAdd(&g_cnt[batch[i] & (NG - 1)], 1.0f);
}

// 128 threads: thread idx -> (graph, out-col)
__global__ void final_kernel(const float* __restrict__ Wl,
                             const float* __restrict__ bl,
                             float* __restrict__ out) {
    int idx = threadIdx.x;
    int g = idx >> 1, c = idx & 1;
    float inv = 1.0f / fmaxf(g_cnt[g], 1.0f);
    float acc = bl[c];
    #pragma unroll 8
    for (int k = 0; k < 256; k++)
        acc = fmaf(g_sums[g * 256 + k] * inv, Wl[k * 2 + c], acc);
    out[idx] = acc;
}

// ---------------- launch ----------------
extern "C" void kernel_launch(void* const* d_in, const int* in_sizes, int n_in,
                              void* d_out, int out_size) {
    const float* x     = (const float*)d_in[0];
    const int*   ei    = (const int*)d_in[1];     // int64 in reference -> int32 in harness
    const int*   batch = (const int*)d_in[2];
    const float* W1    = (const float*)d_in[3];
    const float* b1    = (const float*)d_in[4];
    const float* W2    = (const float*)d_in[5];
    const float* b2    = (const float*)d_in[6];
    const float* Wl    = (const float*)d_in[7];
    const float* bl    = (const float*)d_in[8];
    float* out = (float*)d_out;

    int N = in_sizes[0] / 128;
    int E = in_sizes[1] / 2;

    // prep: degree -> dinv -> CSR by target
    init_kernel<<<(N + 255) / 256, 256>>>(N);
    deg_kernel<<<(E + 255) / 256, 256>>>(ei, E, N);
    dinv_kernel<<<(N + 255) / 256, 256>>>(N);
    scan_kernel<<<1, 1024>>>(N);
    fill_kernel<<<(E + 255) / 256, 256>>>(ei, E, N);

    // layer 1: aggregate x (128-d) then GEMM 128->256
    agg_d128<<<(N + 7) / 8, 256>>>((const float4*)x, N);
    {
        dim3 grid(2, (N + 127) / 128);
        sgemm_bias_relu<1><<<grid, 256>>>(W1, b1, N);
    }

    // layer 2: aggregate h1 (256-d) then GEMM 256->256
    agg_d256<<<(N + 7) / 8, 256>>>(N);
    {
        dim3 grid(2, (N + 127) / 128);
        sgemm_bias_relu<2><<<grid, 256>>>(W2, b2, N);
    }

    // global mean pool + final linear
    pool_kernel<<<(N + 63) / 64, 256>>>(batch, N);
    count_kernel<<<(N + 255) / 256, 256>>>(batch, N);
    final_kernel<<<1, 128>>>(Wl, bl, out);
}

// round 9
// speedup vs baseline: 1.3585x; 1.3585x over previous
#include <cuda_runtime.h>
#include <cuda_bf16.h>
#include <cstdint>

// ---------------- problem constants ----------------
#define MAXN 100000
#define MAXE 3200000
#define NG   64

__device__ __forceinline__ uint32_t smem_to_u32(const void* p) {
    uint32_t a;
    asm("{ .reg .u64 t; cvta.to.shared.u64 t, %1; cvt.u32.u64 %0, t; }" : "=r"(a) : "l"(p));
    return a;
}
#define LDSM4(r0, r1, r2, r3, addr) \
    asm volatile("ldmatrix.sync.aligned.m8n8.x4.shared.b16 {%0,%1,%2,%3}, [%4];" \
        : "=r"(r0), "=r"(r1), "=r"(r2), "=r"(r3) : "r"(addr))
#define MMA_BF16(d, a, b) \
    asm volatile("mma.sync.aligned.m16n8k16.row.col.f32.bf16.bf16.f32 " \
        "{%0,%1,%2,%3}, {%4,%5,%6,%7}, {%8,%9}, {%0,%1,%2,%3};" \
        : "+f"((d)[0]), "+f"((d)[1]), "+f"((d)[2]), "+f"((d)[3]) \
        : "r"((a)[0]), "r"((a)[1]), "r"((a)[2]), "r"((a)[3]), "r"((b)[0]), "r"((b)[1]))

// ---------------- device scratch (referenced ONLY from device code) ----------------
__device__ int   g_deg[MAXN];
__device__ float g_dinv[MAXN];
__device__ int   g_colptr[MAXN + 1];
__device__ int   g_cursor[MAXN];
__device__ int   g_blocksum[128];
__device__ int   g_bloff[128];
__device__ int2  g_edge[MAXE];
__device__ __align__(16) __nv_bfloat16 g_a1hi[(size_t)MAXN * 128];
__device__ __align__(16) __nv_bfloat16 g_a1lo[(size_t)MAXN * 128];
__device__ __align__(16) float g_h1[(size_t)MAXN * 256];
__device__ __align__(16) __nv_bfloat16 g_a2hi[(size_t)MAXN * 256];
__device__ __align__(16) __nv_bfloat16 g_a2lo[(size_t)MAXN * 256];
__device__ __align__(16) float g_h2[(size_t)MAXN * 256];
__device__ __align__(16) __nv_bfloat16 g_b1hi[256 * 128];
__device__ __align__(16) __nv_bfloat16 g_b1lo[256 * 128];
__device__ __align__(16) __nv_bfloat16 g_b2hi[256 * 256];
__device__ __align__(16) __nv_bfloat16 g_b2lo[256 * 256];
__device__ float g_sums[NG * 256];
__device__ float g_cnt[NG];

// ---------------- helpers ----------------
__device__ __forceinline__ void split1(float a, __nv_bfloat16& h, __nv_bfloat16& l) {
    h = __float2bfloat16_rn(a);
    l = __float2bfloat16_rn(a - __bfloat162float(h));
}
__device__ __forceinline__ void split4(float4 v, uint2& hi, uint2& lo) {
    union { __nv_bfloat16 b[4]; uint2 u; } H, L;
    split1(v.x, H.b[0], L.b[0]);
    split1(v.y, H.b[1], L.b[1]);
    split1(v.z, H.b[2], L.b[2]);
    split1(v.w, H.b[3], L.b[3]);
    hi = H.u; lo = L.u;
}

// ---------------- prep kernels ----------------
__global__ void init_kernel(int n) {
    int i = blockIdx.x * blockDim.x + threadIdx.x;
    if (i < n) g_deg[i] = 0;
    if (i < NG * 256) g_sums[i] = 0.f;
    if (i < NG) g_cnt[i] = 0.f;
}

__global__ void deg_kernel(const int* __restrict__ ei, int E, int n) {
    int e = blockIdx.x * blockDim.x + threadIdx.x;
    if (e < E) {
        unsigned c = (unsigned)ei[E + e];
        if (c < (unsigned)n) atomicAdd(&g_deg[c], 1);
    }
}

__global__ void dinv_kernel(int n) {
    int i = blockIdx.x * blockDim.x + threadIdx.x;
    if (i < n) g_dinv[i] = rsqrtf((float)(g_deg[i] + 1));
}

// 3-phase multiblock scan
__global__ void scan1(int n) {
    __shared__ int wsum[32];
    int i = blockIdx.x * 1024 + threadIdx.x;
    int lane = threadIdx.x & 31, wid = threadIdx.x >> 5;
    int v = (i < n) ? g_deg[i] : 0;
    int s = v;
    #pragma unroll
    for (int off = 1; off < 32; off <<= 1) {
        int t = __shfl_up_sync(0xffffffffu, s, off);
        if (lane >= off) s += t;
    }
    if (lane == 31) wsum[wid] = s;
    __syncthreads();
    if (wid == 0) {
        int t = wsum[lane];
        int ss = t;
        #pragma unroll
        for (int off = 1; off < 32; off <<= 1) {
            int u = __shfl_up_sync(0xffffffffu, ss, off);
            if (lane >= off) ss += u;
        }
        wsum[lane] = ss - t;
    }
    __syncthreads();
    if (i < n) g_colptr[i] = wsum[wid] + s - v;
    if (threadIdx.x == 1023) g_blocksum[blockIdx.x] = wsum[31] + s;
}

__global__ void scan2(int nb, int n) {
    __shared__ int ws[4];
    int lane = threadIdx.x & 31, wid = threadIdx.x >> 5;
    int v = (threadIdx.x < nb) ? g_blocksum[threadIdx.x] : 0;
    int s = v;
    #pragma unroll
    for (int off = 1; off < 32; off <<= 1) {
        int t = __shfl_up_sync(0xffffffffu, s, off);
        if (lane >= off) s += t;
    }
    if (lane == 31) ws[wid] = s;
    __syncthreads();
    int base = 0;
    for (int w = 0; w < wid; w++) base += ws[w];
    int excl = base + s - v;
    if (threadIdx.x < nb) g_bloff[threadIdx.x] = excl;
    if (threadIdx.x == nb - 1) g_colptr[n] = excl + v;
}

__global__ void scan3(int n) {
    int i = blockIdx.x * blockDim.x + threadIdx.x;
    if (i < n) {
        int v = g_colptr[i] + g_bloff[i >> 10];
        g_colptr[i] = v;
        g_cursor[i] = v;
    }
}

__global__ void fill_kernel(const int* __restrict__ ei, int E, int n) {
    int e = blockIdx.x * blockDim.x + threadIdx.x;
    if (e >= E) return;
    unsigned r = (unsigned)ei[e];
    unsigned c = (unsigned)ei[E + e];
    if (r >= (unsigned)n || c >= (unsigned)n) return;
    int p = atomicAdd(&g_cursor[c], 1);
    g_edge[p] = make_int2((int)r, __float_as_int(g_dinv[r] * g_dinv[c]));
}

// transpose W [K,N] -> B [N,K] with bf16 hi/lo split
__global__ void prep_weights(const float* __restrict__ W1, const float* __restrict__ W2) {
    int nn = blockIdx.x;
    for (int k = threadIdx.x; k < 128; k += 256) {
        __nv_bfloat16 h, l;
        split1(W1[k * 256 + nn], h, l);
        g_b1hi[nn * 128 + k] = h;
        g_b1lo[nn * 128 + k] = l;
    }
    for (int k = threadIdx.x; k < 256; k += 256) {
        __nv_bfloat16 h, l;
        split1(W2[k * 256 + nn], h, l);
        g_b2hi[nn * 256 + k] = h;
        g_b2lo[nn * 256 + k] = l;
    }
}

// ---------------- aggregation (CSR gather, fp32 math, bf16 hi/lo output) ----------
__global__ void agg_d128(const float4* __restrict__ X, int n) {
    int node = blockIdx.x * 8 + (threadIdx.x >> 5);
    if (node >= n) return;
    int lane = threadIdx.x & 31;
    float di = g_dinv[node];
    float self = di * di;
    float4 xv = X[(size_t)node * 32 + lane];
    float4 acc = make_float4(xv.x * self, xv.y * self, xv.z * self, xv.w * self);
    int s = g_colptr[node], e = g_colptr[node + 1];
    for (int p = s; p < e; p++) {
        int2 ed = g_edge[p];
        float w = __int_as_float(ed.y);
        float4 v = X[(size_t)ed.x * 32 + lane];
        acc.x = fmaf(v.x, w, acc.x);
        acc.y = fmaf(v.y, w, acc.y);
        acc.z = fmaf(v.z, w, acc.z);
        acc.w = fmaf(v.w, w, acc.w);
    }
    uint2 hi, lo;
    split4(acc, hi, lo);
    *(uint2*)(g_a1hi + (size_t)node * 128 + lane * 4) = hi;
    *(uint2*)(g_a1lo + (size_t)node * 128 + lane * 4) = lo;
}

__global__ void agg_d256(int n) {
    int node = blockIdx.x * 8 + (threadIdx.x >> 5);
    if (node >= n) return;
    int lane = threadIdx.x & 31;
    const float4* X = (const float4*)g_h1;
    float di = g_dinv[node];
    float self = di * di;
    size_t base = (size_t)node * 64 + lane;
    float4 x0 = X[base], x1 = X[base + 32];
    float4 a0 = make_float4(x0.x * self, x0.y * self, x0.z * self, x0.w * self);
    float4 a1 = make_float4(x1.x * self, x1.y * self, x1.z * self, x1.w * self);
    int s = g_colptr[node], e = g_colptr[node + 1];
    for (int p = s; p < e; p++) {
        int2 ed = g_edge[p];
        float w = __int_as_float(ed.y);
        size_t rb = (size_t)ed.x * 64 + lane;
        float4 v0 = X[rb], v1 = X[rb + 32];
        a0.x = fmaf(v0.x, w, a0.x); a0.y = fmaf(v0.y, w, a0.y);
        a0.z = fmaf(v0.z, w, a0.z); a0.w = fmaf(v0.w, w, a0.w);
        a1.x = fmaf(v1.x, w, a1.x); a1.y = fmaf(v1.y, w, a1.y);
        a1.z = fmaf(v1.z, w, a1.z); a1.w = fmaf(v1.w, w, a1.w);
    }
    uint2 h0, l0, h1v, l1v;
    split4(a0, h0, l0);
    split4(a1, h1v, l1v);
    *(uint2*)(g_a2hi + (size_t)node * 256 + lane * 4) = h0;
    *(uint2*)(g_a2lo + (size_t)node * 256 + lane * 4) = l0;
    *(uint2*)(g_a2hi + (size_t)node * 256 + 128 + lane * 4) = h1v;
    *(uint2*)(g_a2lo + (size_t)node * 256 + 128 + lane * 4) = l1v;
}

// ---------------- HMMA bf16x3 GEMM + bias + relu ----------------
// C[M,256] = A[M,K] @ W[K,256]. Block tile 128x128, 8 warps (4Mx2N), warp 32x64.
// Smem tiles [128 rows][32 bf16], padded row stride 80B (16B-aligned, ldmatrix
// conflict-free). Single buffer + register prefetch.
template<int LAYER>
__global__ __launch_bounds__(256, 1) void gemm_mma(const float* __restrict__ bias, int M) {
    constexpr int K = (LAYER == 1) ? 128 : 256;
    constexpr int NCH = K / 32;
    const __nv_bfloat16* Ahi = (LAYER == 1) ? g_a1hi : g_a2hi;
    const __nv_bfloat16* Alo = (LAYER == 1) ? g_a1lo : g_a2lo;
    const __nv_bfloat16* Bhi = (LAYER == 1) ? g_b1hi : g_b2hi;
    const __nv_bfloat16* Blo = (LAYER == 1) ? g_b1lo : g_b2lo;
    float* C = (LAYER == 1) ? g_h1 : g_h2;

    __shared__ __align__(16) char smem[40960];
    uint32_t sb = smem_to_u32(smem);
    const uint32_t SA_H = 0, SA_L = 10240, SB_H = 20480, SB_L = 30720;

    int tid = threadIdx.x, lane = tid & 31, wid = tid >> 5;
    int row0 = blockIdx.x * 128, col0 = blockIdx.y * 128;
    int wm = wid & 3, wn = wid >> 2;

    float acc[2][8][4];
    #pragma unroll
    for (int i = 0; i < 2; i++)
        #pragma unroll
        for (int j = 0; j < 8; j++)
            #pragma unroll
            for (int q = 0; q < 4; q++) acc[i][j][q] = 0.f;

    uint4 pAh[2], pAl[2], pBh[2], pBl[2];
    auto prefetch = [&](int ch) {
        #pragma unroll
        for (int g = 0; g < 2; g++) {
            int idx = tid + g * 256;
            int r = idx >> 2, c = idx & 3;
            int gk = ch * 32 + c * 8;
            int ar = row0 + r;
            if (ar < M) {
                pAh[g] = *(const uint4*)(Ahi + (size_t)ar * K + gk);
                pAl[g] = *(const uint4*)(Alo + (size_t)ar * K + gk);
            } else {
                pAh[g] = make_uint4(0, 0, 0, 0);
                pAl[g] = make_uint4(0, 0, 0, 0);
            }
            int br = col0 + r;
            pBh[g] = *(const uint4*)(Bhi + (size_t)br * K + gk);
            pBl[g] = *(const uint4*)(Blo + (size_t)br * K + gk);
        }
    };
    auto stage = [&]() {
        #pragma unroll
        for (int g = 0; g < 2; g++) {
            int idx = tid + g * 256;
            int r = idx >> 2, c = idx & 3;
            uint32_t o = (uint32_t)(r * 80 + c * 16);
            *(uint4*)(smem + SA_H + o) = pAh[g];
            *(uint4*)(smem + SA_L + o) = pAl[g];
            *(uint4*)(smem + SB_H + o) = pBh[g];
            *(uint4*)(smem + SB_L + o) = pBl[g];
        }
    };

    prefetch(0);
    stage();
    __syncthreads();

    for (int ch = 0; ch < NCH; ch++) {
        if (ch + 1 < NCH) prefetch(ch + 1);
        #pragma unroll
        for (int ks = 0; ks < 2; ks++) {
            int r = lane & 15;
            int kb = ks * 16 + ((lane >> 4) << 3);
            uint32_t aH[2][4], aL[2][4];
            #pragma unroll
            for (int mf = 0; mf < 2; mf++) {
                uint32_t off = (uint32_t)((wm * 32 + mf * 16 + r) * 80 + kb * 2);
                LDSM4(aH[mf][0], aH[mf][1], aH[mf][2], aH[mf][3], sb + SA_H + off);
                LDSM4(aL[mf][0], aL[mf][1], aL[mf][2], aL[mf][3], sb + SA_L + off);
            }
            uint32_t bH[8][2], bL[8][2];
            #pragma unroll
            for (int nq = 0; nq < 4; nq++) {
                uint32_t off = (uint32_t)((wn * 64 + nq * 16 + r) * 80 + kb * 2);
                uint32_t t0, t1, t2, t3;
                LDSM4(t0, t1, t2, t3, sb + SB_H + off);
                bH[nq * 2][0] = t0; bH[nq * 2][1] = t2;
                bH[nq * 2 + 1][0] = t1; bH[nq * 2 + 1][1] = t3;
                LDSM4(t0, t1, t2, t3, sb + SB_L + off);
                bL[nq * 2][0] = t0; bL[nq * 2][1] = t2;
                bL[nq * 2 + 1][0] = t1; bL[nq * 2 + 1][1] = t3;
            }
            #pragma unroll
            for (int mf = 0; mf < 2; mf++)
                #pragma unroll
                for (int nf = 0; nf < 8; nf++) {
                    MMA_BF16(acc[mf][nf], aH[mf], bH[nf]);
                    MMA_BF16(acc[mf][nf], aH[mf], bL[nf]);
                    MMA_BF16(acc[mf][nf], aL[mf], bH[nf]);
                }
        }
        __syncthreads();
        if (ch + 1 < NCH) {
            stage();
            __syncthreads();
        }
    }

    // epilogue: fragment row = lane>>2 (+8), cols = (lane&3)*2..+1
    #pragma unroll
    for (int mf = 0; mf < 2; mf++)
        #pragma unroll
        for (int nf = 0; nf < 8; nf++) {
            int rr = row0 + wm * 32 + mf * 16 + (lane >> 2);
            int cc = col0 + wn * 64 + nf * 8 + (lane & 3) * 2;
            float bv0 = bias[cc], bv1 = bias[cc + 1];
            if (rr < M) {
                float2 v = make_float2(fmaxf(acc[mf][nf][0] + bv0, 0.f),
                                       fmaxf(acc[mf][nf][1] + bv1, 0.f));
                *(float2*)(C + (size_t)rr * 256 + cc) = v;
            }
            if (rr + 8 < M) {
                float2 v = make_float2(fmaxf(acc[mf][nf][2] + bv0, 0.f),
                                       fmaxf(acc[mf][nf][3] + bv1, 0.f));
                *(float2*)(C + (size_t)(rr + 8) * 256 + cc) = v;
            }
        }
}

// ---------------- pooling + final ----------------
__global__ void pool_kernel(const int* __restrict__ batch, int n) {
    int c = threadIdx.x;
    int start = blockIdx.x * 64;
    if (start >= n) return;
    int end = min(start + 64, n);
    float acc = 0.f;
    int g = batch[start] & (NG - 1);
    for (int i = start; i < end; i++) {
        int gi = batch[i] & (NG - 1);
        if (gi != g) {
            atomicAdd(&g_sums[g * 256 + c], acc);
            acc = 0.f;
            g = gi;
        }
        acc += g_h2[(size_t)i * 256 + c];
    }
    atomicAdd(&g_sums[g * 256 + c], acc);
}

__global__ void count_kernel(const int* __restrict__ batch, int n) {
    int i = blockIdx.x * blockDim.x + threadIdx.x;
    if (i < n) atomicAdd(&g_cnt[batch[i] & (NG - 1)], 1.0f);
}

__global__ void final_kernel(const float* __restrict__ Wl,
                             const float* __restrict__ bl,
                             float* __restrict__ out) {
    int idx = threadIdx.x;
    int g = idx >> 1, c = idx & 1;
    float inv = 1.0f / fmaxf(g_cnt[g], 1.0f);
    float acc = bl[c];
    #pragma unroll 8
    for (int k = 0; k < 256; k++)
        acc = fmaf(g_sums[g * 256 + k] * inv, Wl[k * 2 + c], acc);
    out[idx] = acc;
}

// ---------------- launch ----------------
extern "C" void kernel_launch(void* const* d_in, const int* in_sizes, int n_in,
                              void* d_out, int out_size) {
    const float* x     = (const float*)d_in[0];
    const int*   ei    = (const int*)d_in[1];
    const int*   batch = (const int*)d_in[2];
    const float* W1    = (const float*)d_in[3];
    const float* b1    = (const float*)d_in[4];
    const float* W2    = (const float*)d_in[5];
    const float* b2    = (const float*)d_in[6];
    const float* Wl    = (const float*)d_in[7];
    const float* bl    = (const float*)d_in[8];
    float* out = (float*)d_out;

    int N = in_sizes[0] / 128;
    int E = in_sizes[1] / 2;
    int nb = (N + 1023) / 1024;

    // prep
    init_kernel<<<(N + 255) / 256, 256>>>(N);
    deg_kernel<<<(E + 255) / 256, 256>>>(ei, E, N);
    dinv_kernel<<<(N + 255) / 256, 256>>>(N);
    scan1<<<nb, 1024>>>(N);
    scan2<<<1, 128>>>(nb, N);
    scan3<<<(N + 255) / 256, 256>>>(N);
    prep_weights<<<256, 256>>>(W1, W2);
    fill_kernel<<<(E + 255) / 256, 256>>>(ei, E, N);

    int mtiles = (N + 127) / 128;
    dim3 ggrid(mtiles, 2);
    // layer 1
    agg_d128<<<(N + 7) / 8, 256>>>((const float4*)x, N);
    gemm_mma<1><<<ggrid, 256>>>(b1, N);
    // layer 2
    agg_d256<<<(N + 7) / 8, 256>>>(N);
    gemm_mma<2><<<ggrid, 256>>>(b2, N);
    // pool + final
    pool_kernel<<<(N + 63) / 64, 256>>>(batch, N);
    count_kernel<<<(N + 255) / 256, 256>>>(batch, N);
    final_kernel<<<1, 128>>>(Wl, bl, out);
}

// round 10
// speedup vs baseline: 1.5984x; 1.1766x over previous
#include <cuda_runtime.h>
#include <cuda_bf16.h>
#include <cuda_fp16.h>
#include <cstdint>

// ---------------- problem constants ----------------
#define MAXN 100000
#define MAXE 3200000
#define NG   64

__device__ __forceinline__ uint32_t smem_to_u32(const void* p) {
    uint32_t a;
    asm("{ .reg .u64 t; cvta.to.shared.u64 t, %1; cvt.u32.u64 %0, t; }" : "=r"(a) : "l"(p));
    return a;
}
#define LDSM4(r0, r1, r2, r3, addr) \
    asm volatile("ldmatrix.sync.aligned.m8n8.x4.shared.b16 {%0,%1,%2,%3}, [%4];" \
        : "=r"(r0), "=r"(r1), "=r"(r2), "=r"(r3) : "r"(addr))
#define MMA_BF16(d, a, b) \
    asm volatile("mma.sync.aligned.m16n8k16.row.col.f32.bf16.bf16.f32 " \
        "{%0,%1,%2,%3}, {%4,%5,%6,%7}, {%8,%9}, {%0,%1,%2,%3};" \
        : "+f"((d)[0]), "+f"((d)[1]), "+f"((d)[2]), "+f"((d)[3]) \
        : "r"((a)[0]), "r"((a)[1]), "r"((a)[2]), "r"((a)[3]), "r"((b)[0]), "r"((b)[1]))

// ---------------- device scratch (referenced ONLY from device code) ----------------
__device__ int   g_deg[MAXN];
__device__ float g_dinv[MAXN];
__device__ int   g_colptr[MAXN + 1];
__device__ int   g_cursor[MAXN];
__device__ int   g_blocksum[128];
__device__ int   g_bloff[128];
__device__ int2  g_edge[MAXE];
__device__ __align__(16) __half g_xh[(size_t)MAXN * 128];        // x in fp16
__device__ __align__(16) __half g_h1h[(size_t)MAXN * 256];       // h1 in fp16
__device__ __align__(16) __nv_bfloat16 g_a1hi[(size_t)MAXN * 128];
__device__ __align__(16) __nv_bfloat16 g_a1lo[(size_t)MAXN * 128];
__device__ __align__(16) __nv_bfloat16 g_a2hi[(size_t)MAXN * 256];
__device__ __align__(16) __nv_bfloat16 g_a2lo[(size_t)MAXN * 256];
__device__ __align__(16) float g_h2[(size_t)MAXN * 256];
__device__ __align__(16) __nv_bfloat16 g_b1hi[256 * 128];
__device__ __align__(16) __nv_bfloat16 g_b1lo[256 * 128];
__device__ __align__(16) __nv_bfloat16 g_b2hi[256 * 256];
__device__ __align__(16) __nv_bfloat16 g_b2lo[256 * 256];
__device__ float g_sums[NG * 256];
__device__ float g_cnt[NG];

// ---------------- helpers ----------------
__device__ __forceinline__ void split1(float a, __nv_bfloat16& h, __nv_bfloat16& l) {
    h = __float2bfloat16_rn(a);
    l = __float2bfloat16_rn(a - __bfloat162float(h));
}
__device__ __forceinline__ void split4(float4 v, uint2& hi, uint2& lo) {
    union { __nv_bfloat16 b[4]; uint2 u; } H, L;
    split1(v.x, H.b[0], L.b[0]);
    split1(v.y, H.b[1], L.b[1]);
    split1(v.z, H.b[2], L.b[2]);
    split1(v.w, H.b[3], L.b[3]);
    hi = H.u; lo = L.u;
}

// ---------------- prep kernels ----------------
__global__ void init_kernel(int n) {
    int i = blockIdx.x * blockDim.x + threadIdx.x;
    if (i < n) g_deg[i] = 0;
    if (i < NG * 256) g_sums[i] = 0.f;
    if (i < NG) g_cnt[i] = 0.f;
}

__global__ void deg_kernel(const int* __restrict__ ei, int E, int n) {
    int e = blockIdx.x * blockDim.x + threadIdx.x;
    if (e < E) {
        unsigned c = (unsigned)ei[E + e];
        if (c < (unsigned)n) atomicAdd(&g_deg[c], 1);
    }
}

__global__ void dinv_kernel(int n) {
    int i = blockIdx.x * blockDim.x + threadIdx.x;
    if (i < n) g_dinv[i] = rsqrtf((float)(g_deg[i] + 1));
}

// x fp32 -> fp16
__global__ void x_to_half(const float4* __restrict__ X, int total4) {
    int i = blockIdx.x * blockDim.x + threadIdx.x;
    if (i >= total4) return;
    float4 v = X[i];
    union { __half2 h[2]; uint2 u; } o;
    o.h[0] = __floats2half2_rn(v.x, v.y);
    o.h[1] = __floats2half2_rn(v.z, v.w);
    *(uint2*)(g_xh + (size_t)i * 4) = o.u;
}

// 3-phase multiblock scan
__global__ void scan1(int n) {
    __shared__ int wsum[32];
    int i = blockIdx.x * 1024 + threadIdx.x;
    int lane = threadIdx.x & 31, wid = threadIdx.x >> 5;
    int v = (i < n) ? g_deg[i] : 0;
    int s = v;
    #pragma unroll
    for (int off = 1; off < 32; off <<= 1) {
        int t = __shfl_up_sync(0xffffffffu, s, off);
        if (lane >= off) s += t;
    }
    if (lane == 31) wsum[wid] = s;
    __syncthreads();
    if (wid == 0) {
        int t = wsum[lane];
        int ss = t;
        #pragma unroll
        for (int off = 1; off < 32; off <<= 1) {
            int u = __shfl_up_sync(0xffffffffu, ss, off);
            if (lane >= off) ss += u;
        }
        wsum[lane] = ss - t;
    }
    __syncthreads();
    if (i < n) g_colptr[i] = wsum[wid] + s - v;
    if (threadIdx.x == 1023) g_blocksum[blockIdx.x] = wsum[31] + s;
}

__global__ void scan2(int nb, int n) {
    __shared__ int ws[4];
    int lane = threadIdx.x & 31, wid = threadIdx.x >> 5;
    int v = (threadIdx.x < nb) ? g_blocksum[threadIdx.x] : 0;
    int s = v;
    #pragma unroll
    for (int off = 1; off < 32; off <<= 1) {
        int t = __shfl_up_sync(0xffffffffu, s, off);
        if (lane >= off) s += t;
    }
    if (lane == 31) ws[wid] = s;
    __syncthreads();
    int base = 0;
    for (int w = 0; w < wid; w++) base += ws[w];
    int excl = base + s - v;
    if (threadIdx.x < nb) g_bloff[threadIdx.x] = excl;
    if (threadIdx.x == nb - 1) g_colptr[n] = excl + v;
}

__global__ void scan3(int n) {
    int i = blockIdx.x * blockDim.x + threadIdx.x;
    if (i < n) {
        int v = g_colptr[i] + g_bloff[i >> 10];
        g_colptr[i] = v;
        g_cursor[i] = v;
    }
}

__global__ void fill_kernel(const int* __restrict__ ei, int E, int n) {
    int e = blockIdx.x * blockDim.x + threadIdx.x;
    if (e >= E) return;
    unsigned r = (unsigned)ei[e];
    unsigned c = (unsigned)ei[E + e];
    if (r >= (unsigned)n || c >= (unsigned)n) return;
    int p = atomicAdd(&g_cursor[c], 1);
    g_edge[p] = make_int2((int)r, __float_as_int(g_dinv[r] * g_dinv[c]));
}

// transpose W [K,N] -> B [N,K] with bf16 hi/lo split
__global__ void prep_weights(const float* __restrict__ W1, const float* __restrict__ W2) {
    int nn = blockIdx.x;
    for (int k = threadIdx.x; k < 128; k += 256) {
        __nv_bfloat16 h, l;
        split1(W1[k * 256 + nn], h, l);
        g_b1hi[nn * 128 + k] = h;
        g_b1lo[nn * 128 + k] = l;
    }
    for (int k = threadIdx.x; k < 256; k += 256) {
        __nv_bfloat16 h, l;
        split1(W2[k * 256 + nn], h, l);
        g_b2hi[nn * 256 + k] = h;
        g_b2lo[nn * 256 + k] = l;
    }
}

// ---------------- aggregation (CSR gather of fp16 rows, fp32 accumulate) --------
// layer 1, D=128: warp per node, lane owns 4 cols (one uint2 = 8B)
__global__ void agg_d128(int n) {
    int node = blockIdx.x * 8 + (threadIdx.x >> 5);
    if (node >= n) return;
    int lane = threadIdx.x & 31;
    float di = g_dinv[node];
    float self = di * di;
    const uint2* Xh = (const uint2*)g_xh;
    union { __half2 h[2]; uint2 u; } cv;
    cv.u = Xh[(size_t)node * 32 + lane];
    float2 f0 = __half22float2(cv.h[0]), f1 = __half22float2(cv.h[1]);
    float4 acc = make_float4(f0.x * self, f0.y * self, f1.x * self, f1.y * self);
    int s = g_colptr[node], e = g_colptr[node + 1];
    for (int p = s; p < e; p++) {
        int2 ed = g_edge[p];
        float w = __int_as_float(ed.y);
        cv.u = Xh[(size_t)ed.x * 32 + lane];
        f0 = __half22float2(cv.h[0]);
        f1 = __half22float2(cv.h[1]);
        acc.x = fmaf(f0.x, w, acc.x);
        acc.y = fmaf(f0.y, w, acc.y);
        acc.z = fmaf(f1.x, w, acc.z);
        acc.w = fmaf(f1.y, w, acc.w);
    }
    uint2 hi, lo;
    split4(acc, hi, lo);
    *(uint2*)(g_a1hi + (size_t)node * 128 + lane * 4) = hi;
    *(uint2*)(g_a1lo + (size_t)node * 128 + lane * 4) = lo;
}

// layer 2, D=256: warp per node, lane owns 8 cols (one uint4 = 16B)
__global__ void agg_d256(int n) {
    int node = blockIdx.x * 8 + (threadIdx.x >> 5);
    if (node >= n) return;
    int lane = threadIdx.x & 31;
    const uint4* Xh = (const uint4*)g_h1h;
    float di = g_dinv[node];
    float self = di * di;
    union { __half2 h[4]; uint4 u; } cv;
    cv.u = Xh[(size_t)node * 32 + lane];
    float a[8];
    {
        float2 f0 = __half22float2(cv.h[0]), f1 = __half22float2(cv.h[1]);
        float2 f2 = __half22float2(cv.h[2]), f3 = __half22float2(cv.h[3]);
        a[0] = f0.x * self; a[1] = f0.y * self;
        a[2] = f1.x * self; a[3] = f1.y * self;
        a[4] = f2.x * self; a[5] = f2.y * self;
        a[6] = f3.x * self; a[7] = f3.y * self;
    }
    int s = g_colptr[node], e = g_colptr[node + 1];
    for (int p = s; p < e; p++) {
        int2 ed = g_edge[p];
        float w = __int_as_float(ed.y);
        cv.u = Xh[(size_t)ed.x * 32 + lane];
        float2 f0 = __half22float2(cv.h[0]), f1 = __half22float2(cv.h[1]);
        float2 f2 = __half22float2(cv.h[2]), f3 = __half22float2(cv.h[3]);
        a[0] = fmaf(f0.x, w, a[0]); a[1] = fmaf(f0.y, w, a[1]);
        a[2] = fmaf(f1.x, w, a[2]); a[3] = fmaf(f1.y, w, a[3]);
        a[4] = fmaf(f2.x, w, a[4]); a[5] = fmaf(f2.y, w, a[5]);
        a[6] = fmaf(f3.x, w, a[6]); a[7] = fmaf(f3.y, w, a[7]);
    }
    uint2 h0, l0, h1v, l1v;
    split4(make_float4(a[0], a[1], a[2], a[3]), h0, l0);
    split4(make_float4(a[4], a[5], a[6], a[7]), h1v, l1v);
    *(uint2*)(g_a2hi + (size_t)node * 256 + lane * 8) = h0;
    *(uint2*)(g_a2lo + (size_t)node * 256 + lane * 8) = l0;
    *(uint2*)(g_a2hi + (size_t)node * 256 + lane * 8 + 4) = h1v;
    *(uint2*)(g_a2lo + (size_t)node * 256 + lane * 8 + 4) = l1v;
}

// ---------------- HMMA bf16x3 GEMM + bias + relu ----------------
// C[M,256] = A[M,K] @ W[K,256]. Block tile 128x128, 8 warps (4Mx2N), warp 32x64.
// LAYER 1 writes fp16 h1; LAYER 2 writes fp32 h2.
template<int LAYER>
__global__ __launch_bounds__(256, 1) void gemm_mma(const float* __restrict__ bias, int M) {
    constexpr int K = (LAYER == 1) ? 128 : 256;
    constexpr int NCH = K / 32;
    const __nv_bfloat16* Ahi = (LAYER == 1) ? g_a1hi : g_a2hi;
    const __nv_bfloat16* Alo = (LAYER == 1) ? g_a1lo : g_a2lo;
    const __nv_bfloat16* Bhi = (LAYER == 1) ? g_b1hi : g_b2hi;
    const __nv_bfloat16* Blo = (LAYER == 1) ? g_b1lo : g_b2lo;

    __shared__ __align__(16) char smem[40960];
    uint32_t sb = smem_to_u32(smem);
    const uint32_t SA_H = 0, SA_L = 10240, SB_H = 20480, SB_L = 30720;

    int tid = threadIdx.x, lane = tid & 31, wid = tid >> 5;
    int row0 = blockIdx.x * 128, col0 = blockIdx.y * 128;
    int wm = wid & 3, wn = wid >> 2;

    float acc[2][8][4];
    #pragma unroll
    for (int i = 0; i < 2; i++)
        #pragma unroll
        for (int j = 0; j < 8; j++)
            #pragma unroll
            for (int q = 0; q < 4; q++) acc[i][j][q] = 0.f;

    uint4 pAh[2], pAl[2], pBh[2], pBl[2];
    auto prefetch = [&](int ch) {
        #pragma unroll
        for (int g = 0; g < 2; g++) {
            int idx = tid + g * 256;
            int r = idx >> 2, c = idx & 3;
            int gk = ch * 32 + c * 8;
            int ar = row0 + r;
            if (ar < M) {
                pAh[g] = *(const uint4*)(Ahi + (size_t)ar * K + gk);
                pAl[g] = *(const uint4*)(Alo + (size_t)ar * K + gk);
            } else {
                pAh[g] = make_uint4(0, 0, 0, 0);
                pAl[g] = make_uint4(0, 0, 0, 0);
            }
            int br = col0 + r;
            pBh[g] = *(const uint4*)(Bhi + (size_t)br * K + gk);
            pBl[g] = *(const uint4*)(Blo + (size_t)br * K + gk);
        }
    };
    auto stage = [&]() {
        #pragma unroll
        for (int g = 0; g < 2; g++) {
            int idx = tid + g * 256;
            int r = idx >> 2, c = idx & 3;
            uint32_t o = (uint32_t)(r * 80 + c * 16);
            *(uint4*)(smem + SA_H + o) = pAh[g];
            *(uint4*)(smem + SA_L + o) = pAl[g];
            *(uint4*)(smem + SB_H + o) = pBh[g];
            *(uint4*)(smem + SB_L + o) = pBl[g];
        }
    };

    prefetch(0);
    stage();
    __syncthreads();

    for (int ch = 0; ch < NCH; ch++) {
        if (ch + 1 < NCH) prefetch(ch + 1);
        #pragma unroll
        for (int ks = 0; ks < 2; ks++) {
            int r = lane & 15;
            int kb = ks * 16 + ((lane >> 4) << 3);
            uint32_t aH[2][4], aL[2][4];
            #pragma unroll
            for (int mf = 0; mf < 2; mf++) {
                uint32_t off = (uint32_t)((wm * 32 + mf * 16 + r) * 80 + kb * 2);
                LDSM4(aH[mf][0], aH[mf][1], aH[mf][2], aH[mf][3], sb + SA_H + off);
                LDSM4(aL[mf][0], aL[mf][1], aL[mf][2], aL[mf][3], sb + SA_L + off);
            }
            uint32_t bH[8][2], bL[8][2];
            #pragma unroll
            for (int nq = 0; nq < 4; nq++) {
                uint32_t off = (uint32_t)((wn * 64 + nq * 16 + r) * 80 + kb * 2);
                uint32_t t0, t1, t2, t3;
                LDSM4(t0, t1, t2, t3, sb + SB_H + off);
                bH[nq * 2][0] = t0; bH[nq * 2][1] = t2;
                bH[nq * 2 + 1][0] = t1; bH[nq * 2 + 1][1] = t3;
                LDSM4(t0, t1, t2, t3, sb + SB_L + off);
                bL[nq * 2][0] = t0; bL[nq * 2][1] = t2;
                bL[nq * 2 + 1][0] = t1; bL[nq * 2 + 1][1] = t3;
            }
            #pragma unroll
            for (int mf = 0; mf < 2; mf++)
                #pragma unroll
                for (int nf = 0; nf < 8; nf++) {
                    MMA_BF16(acc[mf][nf], aH[mf], bH[nf]);
                    MMA_BF16(acc[mf][nf], aH[mf], bL[nf]);
                    MMA_BF16(acc[mf][nf], aL[mf], bH[nf]);
                }
        }
        __syncthreads();
        if (ch + 1 < NCH) {
            stage();
            __syncthreads();
        }
    }

    // epilogue: fragment row = lane>>2 (+8), cols = (lane&3)*2..+1
    #pragma unroll
    for (int mf = 0; mf < 2; mf++)
        #pragma unroll
        for (int nf = 0; nf < 8; nf++) {
            int rr = row0 + wm * 32 + mf * 16 + (lane >> 2);
            int cc = col0 + wn * 64 + nf * 8 + (lane & 3) * 2;
            float bv0 = bias[cc], bv1 = bias[cc + 1];
            float v00 = fmaxf(acc[mf][nf][0] + bv0, 0.f);
            float v01 = fmaxf(acc[mf][nf][1] + bv1, 0.f);
            float v10 = fmaxf(acc[mf][nf][2] + bv0, 0.f);
            float v11 = fmaxf(acc[mf][nf][3] + bv1, 0.f);
            if constexpr (LAYER == 1) {
                if (rr < M)
                    *(__half2*)(g_h1h + (size_t)rr * 256 + cc) = __floats2half2_rn(v00, v01);
                if (rr + 8 < M)
                    *(__half2*)(g_h1h + (size_t)(rr + 8) * 256 + cc) = __floats2half2_rn(v10, v11);
            } else {
                if (rr < M)
                    *(float2*)(g_h2 + (size_t)rr * 256 + cc) = make_float2(v00, v01);
                if (rr + 8 < M)
                    *(float2*)(g_h2 + (size_t)(rr + 8) * 256 + cc) = make_float2(v10, v11);
            }
        }
}

// ---------------- pooling + final ----------------
__global__ void pool_kernel(const int* __restrict__ batch, int n) {
    int c = threadIdx.x;
    int start = blockIdx.x * 64;
    if (start >= n) return;
    int end = min(start + 64, n);
    float acc = 0.f;
    int g = batch[start] & (NG - 1);
    for (int i = start; i < end; i++) {
        int gi = batch[i] & (NG - 1);
        if (gi != g) {
            atomicAdd(&g_sums[g * 256 + c], acc);
            acc = 0.f;
            g = gi;
        }
        acc += g_h2[(size_t)i * 256 + c];
    }
    atomicAdd(&g_sums[g * 256 + c], acc);
}

__global__ void count_kernel(const int* __restrict__ batch, int n) {
    int i = blockIdx.x * blockDim.x + threadIdx.x;
    if (i < n) atomicAdd(&g_cnt[batch[i] & (NG - 1)], 1.0f);
}

__global__ void final_kernel(const float* __restrict__ Wl,
                             const float* __restrict__ bl,
                             float* __restrict__ out) {
    int idx = threadIdx.x;
    int g = idx >> 1, c = idx & 1;
    float inv = 1.0f / fmaxf(g_cnt[g], 1.0f);
    float acc = bl[c];
    #pragma unroll 8
    for (int k = 0; k < 256; k++)
        acc = fmaf(g_sums[g * 256 + k] * inv, Wl[k * 2 + c], acc);
    out[idx] = acc;
}

// ---------------- launch ----------------
extern "C" void kernel_launch(void* const* d_in, const int* in_sizes, int n_in,
                              void* d_out, int out_size) {
    const float* x     = (const float*)d_in[0];
    const int*   ei    = (const int*)d_in[1];
    const int*   batch = (const int*)d_in[2];
    const float* W1    = (const float*)d_in[3];
    const float* b1    = (const float*)d_in[4];
    const float* W2    = (const float*)d_in[5];
    const float* b2    = (const float*)d_in[6];
    const float* Wl    = (const float*)d_in[7];
    const float* bl    = (const float*)d_in[8];
    float* out = (float*)d_out;

    int N = in_sizes[0] / 128;
    int E = in_sizes[1] / 2;
    int nb = (N + 1023) / 1024;

    // prep
    init_kernel<<<(N + 255) / 256, 256>>>(N);
    deg_kernel<<<(E + 255) / 256, 256>>>(ei, E, N);
    dinv_kernel<<<(N + 255) / 256, 256>>>(N);
    x_to_half<<<(N * 32 + 255) / 256, 256>>>((const float4*)x, N * 32);
    scan1<<<nb, 1024>>>(N);
    scan2<<<1, 128>>>(nb, N);
    scan3<<<(N + 255) / 256, 256>>>(N);
    prep_weights<<<256, 256>>>(W1, W2);
    fill_kernel<<<(E + 255) / 256, 256>>>(ei, E, N);

    int mtiles = (N + 127) / 128;
    dim3 ggrid(mtiles, 2);
    // layer 1
    agg_d128<<<(N + 7) / 8, 256>>>(N);
    gemm_mma<1><<<ggrid, 256>>>(b1, N);
    // layer 2
    agg_d256<<<(N + 7) / 8, 256>>>(N);
    gemm_mma<2><<<ggrid, 256>>>(b2, N);
    // pool + final
    pool_kernel<<<(N + 63) / 64, 256>>>(batch, N);
    count_kernel<<<(N + 255) / 256, 256>>>(batch, N);
    final_kernel<<<1, 128>>>(Wl, bl, out);
}

// round 11
// speedup vs baseline: 1.8441x; 1.1537x over previous
#include <cuda_runtime.h>
#include <cuda_bf16.h>
#include <cuda_fp16.h>
#include <cstdint>

// ---------------- problem constants ----------------
#define MAXN 100000
#define MAXE 3200000
#define NG   64

__device__ __forceinline__ uint32_t smem_to_u32(const void* p) {
    uint32_t a;
    asm("{ .reg .u64 t; cvta.to.shared.u64 t, %1; cvt.u32.u64 %0, t; }" : "=r"(a) : "l"(p));
    return a;
}
#define LDSM4(r0, r1, r2, r3, addr) \
    asm volatile("ldmatrix.sync.aligned.m8n8.x4.shared.b16 {%0,%1,%2,%3}, [%4];" \
        : "=r"(r0), "=r"(r1), "=r"(r2), "=r"(r3) : "r"(addr))
#define MMA_F16(d, a, b) \
    asm volatile("mma.sync.aligned.m16n8k16.row.col.f32.f16.f16.f32 " \
        "{%0,%1,%2,%3}, {%4,%5,%6,%7}, {%8,%9}, {%0,%1,%2,%3};" \
        : "+f"((d)[0]), "+f"((d)[1]), "+f"((d)[2]), "+f"((d)[3]) \
        : "r"((a)[0]), "r"((a)[1]), "r"((a)[2]), "r"((a)[3]), "r"((b)[0]), "r"((b)[1]))

// ---------------- device scratch (referenced ONLY from device code) ----------------
__device__ int   g_deg[MAXN];
__device__ float g_dinv[MAXN];
__device__ int   g_colptr[MAXN + 1];
__device__ int   g_cursor[MAXN];
__device__ int   g_blocksum[128];
__device__ int   g_bloff[128];
__device__ int2  g_edge[MAXE];
__device__ __align__(16) __half g_xh[(size_t)MAXN * 128];    // x in fp16
__device__ __align__(16) __half g_h1h[(size_t)MAXN * 256];   // h1 in fp16
__device__ __align__(16) __half g_a1h[(size_t)MAXN * 128];   // agg1 fp16
__device__ __align__(16) __half g_a2h[(size_t)MAXN * 256];   // agg2 fp16
__device__ __align__(16) float g_h2[(size_t)MAXN * 256];
__device__ __align__(16) __half g_b1hi[256 * 128];
__device__ __align__(16) __half g_b1lo[256 * 128];
__device__ __align__(16) __half g_b2hi[256 * 256];
__device__ __align__(16) __half g_b2lo[256 * 256];
__device__ float g_sums[NG * 256];
__device__ float g_cnt[NG];

// ---------------- prep kernels ----------------
__global__ void init_kernel(int n) {
    int i = blockIdx.x * blockDim.x + threadIdx.x;
    if (i < n) g_deg[i] = 0;
    if (i < NG * 256) g_sums[i] = 0.f;
    if (i < NG) g_cnt[i] = 0.f;
}

__global__ void deg_kernel(const int* __restrict__ ei, int E, int n) {
    int e = blockIdx.x * blockDim.x + threadIdx.x;
    if (e < E) {
        unsigned c = (unsigned)ei[E + e];
        if (c < (unsigned)n) atomicAdd(&g_deg[c], 1);
    }
}

__global__ void dinv_kernel(int n) {
    int i = blockIdx.x * blockDim.x + threadIdx.x;
    if (i < n) g_dinv[i] = rsqrtf((float)(g_deg[i] + 1));
}

// x fp32 -> fp16
__global__ void x_to_half(const float4* __restrict__ X, int total4) {
    int i = blockIdx.x * blockDim.x + threadIdx.x;
    if (i >= total4) return;
    float4 v = X[i];
    union { __half2 h[2]; uint2 u; } o;
    o.h[0] = __floats2half2_rn(v.x, v.y);
    o.h[1] = __floats2half2_rn(v.z, v.w);
    *(uint2*)(g_xh + (size_t)i * 4) = o.u;
}

// 3-phase multiblock scan
__global__ void scan1(int n) {
    __shared__ int wsum[32];
    int i = blockIdx.x * 1024 + threadIdx.x;
    int lane = threadIdx.x & 31, wid = threadIdx.x >> 5;
    int v = (i < n) ? g_deg[i] : 0;
    int s = v;
    #pragma unroll
    for (int off = 1; off < 32; off <<= 1) {
        int t = __shfl_up_sync(0xffffffffu, s, off);
        if (lane >= off) s += t;
    }
    if (lane == 31) wsum[wid] = s;
    __syncthreads();
    if (wid == 0) {
        int t = wsum[lane];
        int ss = t;
        #pragma unroll
        for (int off = 1; off < 32; off <<= 1) {
            int u = __shfl_up_sync(0xffffffffu, ss, off);
            if (lane >= off) ss += u;
        }
        wsum[lane] = ss - t;
    }
    __syncthreads();
    if (i < n) g_colptr[i] = wsum[wid] + s - v;
    if (threadIdx.x == 1023) g_blocksum[blockIdx.x] = wsum[31] + s;
}

__global__ void scan2(int nb, int n) {
    __shared__ int ws[4];
    int lane = threadIdx.x & 31, wid = threadIdx.x >> 5;
    int v = (threadIdx.x < nb) ? g_blocksum[threadIdx.x] : 0;
    int s = v;
    #pragma unroll
    for (int off = 1; off < 32; off <<= 1) {
        int t = __shfl_up_sync(0xffffffffu, s, off);
        if (lane >= off) s += t;
    }
    if (lane == 31) ws[wid] = s;
    __syncthreads();
    int base = 0;
    for (int w = 0; w < wid; w++) base += ws[w];
    int excl = base + s - v;
    if (threadIdx.x < nb) g_bloff[threadIdx.x] = excl;
    if (threadIdx.x == nb - 1) g_colptr[n] = excl + v;
}

__global__ void scan3(int n) {
    int i = blockIdx.x * blockDim.x + threadIdx.x;
    if (i < n) {
        int v = g_colptr[i] + g_bloff[i >> 10];
        g_colptr[i] = v;
        g_cursor[i] = v;
    }
}

__global__ void fill_kernel(const int* __restrict__ ei, int E, int n) {
    int e = blockIdx.x * blockDim.x + threadIdx.x;
    if (e >= E) return;
    unsigned r = (unsigned)ei[e];
    unsigned c = (unsigned)ei[E + e];
    if (r >= (unsigned)n || c >= (unsigned)n) return;
    int p = atomicAdd(&g_cursor[c], 1);
    g_edge[p] = make_int2((int)r, __float_as_int(g_dinv[r] * g_dinv[c]));
}

// transpose W [K,N] -> [N,K] with fp16 hi/lo split
__global__ void prep_weights(const float* __restrict__ W1, const float* __restrict__ W2) {
    int nn = blockIdx.x;
    for (int k = threadIdx.x; k < 128; k += 256) {
        float w = W1[k * 256 + nn];
        __half h = __float2half_rn(w);
        g_b1hi[nn * 128 + k] = h;
        g_b1lo[nn * 128 + k] = __float2half_rn(w - __half2float(h));
    }
    for (int k = threadIdx.x; k < 256; k += 256) {
        float w = W2[k * 256 + nn];
        __half h = __float2half_rn(w);
        g_b2hi[nn * 256 + k] = h;
        g_b2lo[nn * 256 + k] = __float2half_rn(w - __half2float(h));
    }
}

// ---------------- aggregation (CSR gather of fp16 rows, fp32 accumulate) --------
// layer 1, D=128: warp per node, lane owns 4 cols (uint2 = 8B)
__global__ void agg_d128(int n) {
    int node = blockIdx.x * 8 + (threadIdx.x >> 5);
    if (node >= n) return;
    int lane = threadIdx.x & 31;
    float di = g_dinv[node];
    float self = di * di;
    const uint2* Xh = (const uint2*)g_xh;
    union { __half2 h[2]; uint2 u; } cv;
    cv.u = Xh[(size_t)node * 32 + lane];
    float2 f0 = __half22float2(cv.h[0]), f1 = __half22float2(cv.h[1]);
    float4 acc = make_float4(f0.x * self, f0.y * self, f1.x * self, f1.y * self);
    int s = g_colptr[node], e = g_colptr[node + 1];
    for (int p = s; p < e; p++) {
        int2 ed = g_edge[p];
        float w = __int_as_float(ed.y);
        cv.u = Xh[(size_t)ed.x * 32 + lane];
        f0 = __half22float2(cv.h[0]);
        f1 = __half22float2(cv.h[1]);
        acc.x = fmaf(f0.x, w, acc.x);
        acc.y = fmaf(f0.y, w, acc.y);
        acc.z = fmaf(f1.x, w, acc.z);
        acc.w = fmaf(f1.y, w, acc.w);
    }
    union { __half2 h[2]; uint2 u; } o;
    o.h[0] = __floats2half2_rn(acc.x, acc.y);
    o.h[1] = __floats2half2_rn(acc.z, acc.w);
    *(uint2*)(g_a1h + (size_t)node * 128 + lane * 4) = o.u;
}

// layer 2, D=256: warp per node, lane owns 8 cols (uint4 = 16B)
__global__ void agg_d256(int n) {
    int node = blockIdx.x * 8 + (threadIdx.x >> 5);
    if (node >= n) return;
    int lane = threadIdx.x & 31;
    const uint4* Xh = (const uint4*)g_h1h;
    float di = g_dinv[node];
    float self = di * di;
    union { __half2 h[4]; uint4 u; } cv;
    cv.u = Xh[(size_t)node * 32 + lane];
    float a[8];
    {
        float2 f0 = __half22float2(cv.h[0]), f1 = __half22float2(cv.h[1]);
        float2 f2 = __half22float2(cv.h[2]), f3 = __half22float2(cv.h[3]);
        a[0] = f0.x * self; a[1] = f0.y * self;
        a[2] = f1.x * self; a[3] = f1.y * self;
        a[4] = f2.x * self; a[5] = f2.y * self;
        a[6] = f3.x * self; a[7] = f3.y * self;
    }
    int s = g_colptr[node], e = g_colptr[node + 1];
    for (int p = s; p < e; p++) {
        int2 ed = g_edge[p];
        float w = __int_as_float(ed.y);
        cv.u = Xh[(size_t)ed.x * 32 + lane];
        float2 f0 = __half22float2(cv.h[0]), f1 = __half22float2(cv.h[1]);
        float2 f2 = __half22float2(cv.h[2]), f3 = __half22float2(cv.h[3]);
        a[0] = fmaf(f0.x, w, a[0]); a[1] = fmaf(f0.y, w, a[1]);
        a[2] = fmaf(f1.x, w, a[2]); a[3] = fmaf(f1.y, w, a[3]);
        a[4] = fmaf(f2.x, w, a[4]); a[5] = fmaf(f2.y, w, a[5]);
        a[6] = fmaf(f3.x, w, a[6]); a[7] = fmaf(f3.y, w, a[7]);
    }
    union { __half2 h[4]; uint4 u; } o;
    o.h[0] = __floats2half2_rn(a[0], a[1]);
    o.h[1] = __floats2half2_rn(a[2], a[3]);
    o.h[2] = __floats2half2_rn(a[4], a[5]);
    o.h[3] = __floats2half2_rn(a[6], a[7]);
    *(uint4*)(g_a2h + (size_t)node * 256 + lane * 8) = o.u;
}

// ---------------- HMMA fp16 (A single, W hi/lo) GEMM + bias + relu ----------------
// C[M,256] = A[M,K] @ W[K,256]. Block tile 128x128, 8 warps (4Mx2N), warp 32x64.
// LAYER 1 writes fp16 h1; LAYER 2 writes fp32 h2.
template<int LAYER>
__global__ __launch_bounds__(256, 1) void gemm_mma(const float* __restrict__ bias, int M) {
    constexpr int K = (LAYER == 1) ? 128 : 256;
    constexpr int NCH = K / 32;
    const __half* A  = (LAYER == 1) ? g_a1h : g_a2h;
    const __half* WH = (LAYER == 1) ? g_b1hi : g_b2hi;
    const __half* WL = (LAYER == 1) ? g_b1lo : g_b2lo;

    __shared__ __align__(16) char smem[30720];
    uint32_t sb = smem_to_u32(smem);
    const uint32_t SA = 0, SH = 10240, SL = 20480;

    int tid = threadIdx.x, lane = tid & 31, wid = tid >> 5;
    int row0 = blockIdx.x * 128, col0 = blockIdx.y * 128;
    int wm = wid & 3, wn = wid >> 2;

    float acc[2][8][4];
    #pragma unroll
    for (int i = 0; i < 2; i++)
        #pragma unroll
        for (int j = 0; j < 8; j++)
            #pragma unroll
            for (int q = 0; q < 4; q++) acc[i][j][q] = 0.f;

    uint4 pA[2], pH[2], pL[2];
    auto prefetch = [&](int ch) {
        #pragma unroll
        for (int g = 0; g < 2; g++) {
            int idx = tid + g * 256;
            int r = idx >> 2, c = idx & 3;
            int gk = ch * 32 + c * 8;
            int ar = row0 + r;
            pA[g] = (ar < M) ? *(const uint4*)(A + (size_t)ar * K + gk)
                             : make_uint4(0, 0, 0, 0);
            int br = col0 + r;
            pH[g] = *(const uint4*)(WH + (size_t)br * K + gk);
            pL[g] = *(const uint4*)(WL + (size_t)br * K + gk);
        }
    };
    auto stage = [&]() {
        #pragma unroll
        for (int g = 0; g < 2; g++) {
            int idx = tid + g * 256;
            int r = idx >> 2, c = idx & 3;
            uint32_t o = (uint32_t)(r * 80 + c * 16);
            *(uint4*)(smem + SA + o) = pA[g];
            *(uint4*)(smem + SH + o) = pH[g];
            *(uint4*)(smem + SL + o) = pL[g];
        }
    };

    prefetch(0);
    stage();
    __syncthreads();

    for (int ch = 0; ch < NCH; ch++) {
        if (ch + 1 < NCH) prefetch(ch + 1);
        #pragma unroll
        for (int ks = 0; ks < 2; ks++) {
            int r = lane & 15;
            int kb = ks * 16 + ((lane >> 4) << 3);
            uint32_t a[2][4];
            #pragma unroll
            for (int mf = 0; mf < 2; mf++) {
                uint32_t off = (uint32_t)((wm * 32 + mf * 16 + r) * 80 + kb * 2);
                LDSM4(a[mf][0], a[mf][1], a[mf][2], a[mf][3], sb + SA + off);
            }
            uint32_t bH[8][2], bL[8][2];
            #pragma unroll
            for (int nq = 0; nq < 4; nq++) {
                uint32_t off = (uint32_t)((wn * 64 + nq * 16 + r) * 80 + kb * 2);
                uint32_t t0, t1, t2, t3;
                LDSM4(t0, t1, t2, t3, sb + SH + off);
                bH[nq * 2][0] = t0; bH[nq * 2][1] = t2;
                bH[nq * 2 + 1][0] = t1; bH[nq * 2 + 1][1] = t3;
                LDSM4(t0, t1, t2, t3, sb + SL + off);
                bL[nq * 2][0] = t0; bL[nq * 2][1] = t2;
                bL[nq * 2 + 1][0] = t1; bL[nq * 2 + 1][1] = t3;
            }
            #pragma unroll
            for (int mf = 0; mf < 2; mf++)
                #pragma unroll
                for (int nf = 0; nf < 8; nf++) {
                    MMA_F16(acc[mf][nf], a[mf], bH[nf]);
                    MMA_F16(acc[mf][nf], a[mf], bL[nf]);
                }
        }
        __syncthreads();
        if (ch + 1 < NCH) {
            stage();
            __syncthreads();
        }
    }

    // epilogue: fragment row = lane>>2 (+8), cols = (lane&3)*2..+1
    #pragma unroll
    for (int mf = 0; mf < 2; mf++)
        #pragma unroll
        for (int nf = 0; nf < 8; nf++) {
            int rr = row0 + wm * 32 + mf * 16 + (lane >> 2);
            int cc = col0 + wn * 64 + nf * 8 + (lane & 3) * 2;
            float bv0 = bias[cc], bv1 = bias[cc + 1];
            float v00 = fmaxf(acc[mf][nf][0] + bv0, 0.f);
            float v01 = fmaxf(acc[mf][nf][1] + bv1, 0.f);
            float v10 = fmaxf(acc[mf][nf][2] + bv0, 0.f);
            float v11 = fmaxf(acc[mf][nf][3] + bv1, 0.f);
            if constexpr (LAYER == 1) {
                if (rr < M)
                    *(__half2*)(g_h1h + (size_t)rr * 256 + cc) = __floats2half2_rn(v00, v01);
                if (rr + 8 < M)
                    *(__half2*)(g_h1h + (size_t)(rr + 8) * 256 + cc) = __floats2half2_rn(v10, v11);
            } else {
                if (rr < M)
                    *(float2*)(g_h2 + (size_t)rr * 256 + cc) = make_float2(v00, v01);
                if (rr + 8 < M)
                    *(float2*)(g_h2 + (size_t)(rr + 8) * 256 + cc) = make_float2(v10, v11);
            }
        }
}

// ---------------- pooling + final ----------------
__global__ void pool_kernel(const int* __restrict__ batch, int n) {
    int c = threadIdx.x;
    int start = blockIdx.x * 64;
    if (start >= n) return;
    int end = min(start + 64, n);
    float acc = 0.f;
    int g = batch[start] & (NG - 1);
    for (int i = start; i < end; i++) {
        int gi = batch[i] & (NG - 1);
        if (gi != g) {
            atomicAdd(&g_sums[g * 256 + c], acc);
            acc = 0.f;
            g = gi;
        }
        acc += g_h2[(size_t)i * 256 + c];
    }
    atomicAdd(&g_sums[g * 256 + c], acc);
}

__global__ void count_kernel(const int* __restrict__ batch, int n) {
    int i = blockIdx.x * blockDim.x + threadIdx.x;
    if (i < n) atomicAdd(&g_cnt[batch[i] & (NG - 1)], 1.0f);
}

__global__ void final_kernel(const float* __restrict__ Wl,
                             const float* __restrict__ bl,
                             float* __restrict__ out) {
    int idx = threadIdx.x;
    int g = idx >> 1, c = idx & 1;
    float inv = 1.0f / fmaxf(g_cnt[g], 1.0f);
    float acc = bl[c];
    #pragma unroll 8
    for (int k = 0; k < 256; k++)
        acc = fmaf(g_sums[g * 256 + k] * inv, Wl[k * 2 + c], acc);
    out[idx] = acc;
}

// ---------------- launch ----------------
extern "C" void kernel_launch(void* const* d_in, const int* in_sizes, int n_in,
                              void* d_out, int out_size) {
    const float* x     = (const float*)d_in[0];
    const int*   ei    = (const int*)d_in[1];
    const int*   batch = (const int*)d_in[2];
    const float* W1    = (const float*)d_in[3];
    const float* b1    = (const float*)d_in[4];
    const float* W2    = (const float*)d_in[5];
    const float* b2    = (const float*)d_in[6];
    const float* Wl    = (const float*)d_in[7];
    const float* bl    = (const float*)d_in[8];
    float* out = (float*)d_out;

    int N = in_sizes[0] / 128;
    int E = in_sizes[1] / 2;
    int nb = (N + 1023) / 1024;

    // prep
    init_kernel<<<(N + 255) / 256, 256>>>(N);
    deg_kernel<<<(E + 255) / 256, 256>>>(ei, E, N);
    dinv_kernel<<<(N + 255) / 256, 256>>>(N);
    x_to_half<<<(N * 32 + 255) / 256, 256>>>((const float4*)x, N * 32);
    scan1<<<nb, 1024>>>(N);
    scan2<<<1, 128>>>(nb, N);
    scan3<<<(N + 255) / 256, 256>>>(N);
    prep_weights<<<256, 256>>>(W1, W2);
    fill_kernel<<<(E + 255) / 256, 256>>>(ei, E, N);

    int mtiles = (N + 127) / 128;
    dim3 ggrid(mtiles, 2);
    // layer 1
    agg_d128<<<(N + 7) / 8, 256>>>(N);
    gemm_mma<1><<<ggrid, 256>>>(b1, N);
    // layer 2
    agg_d256<<<(N + 7) / 8, 256>>>(N);
    gemm_mma<2><<<ggrid, 256>>>(b2, N);
    // pool + final
    pool_kernel<<<(N + 63) / 64, 256>>>(batch, N);
    count_kernel<<<(N + 255) / 256, 256>>>(batch, N);
    final_kernel<<<1, 128>>>(Wl, bl, out);
}

// round 12
// speedup vs baseline: 1.9150x; 1.0384x over previous
#include <cuda_runtime.h>
#include <cuda_bf16.h>
#include <cuda_fp16.h>
#include <cstdint>

// ---------------- problem constants ----------------
#define MAXN 100000
#define MAXE 3200000
#define NG   64

__device__ __forceinline__ uint32_t smem_to_u32(const void* p) {
    uint32_t a;
    asm("{ .reg .u64 t; cvta.to.shared.u64 t, %1; cvt.u32.u64 %0, t; }" : "=r"(a) : "l"(p));
    return a;
}
#define LDSM4(r0, r1, r2, r3, addr) \
    asm volatile("ldmatrix.sync.aligned.m8n8.x4.shared.b16 {%0,%1,%2,%3}, [%4];" \
        : "=r"(r0), "=r"(r1), "=r"(r2), "=r"(r3) : "r"(addr))
#define MMA_F16(d, a, b) \
    asm volatile("mma.sync.aligned.m16n8k16.row.col.f32.f16.f16.f32 " \
        "{%0,%1,%2,%3}, {%4,%5,%6,%7}, {%8,%9}, {%0,%1,%2,%3};" \
        : "+f"((d)[0]), "+f"((d)[1]), "+f"((d)[2]), "+f"((d)[3]) \
        : "r"((a)[0]), "r"((a)[1]), "r"((a)[2]), "r"((a)[3]), "r"((b)[0]), "r"((b)[1]))

// ---------------- device scratch (referenced ONLY from device code) ----------------
__device__ int   g_deg[MAXN];
__device__ float g_dinv[MAXN];
__device__ int   g_colptr[MAXN + 1];
__device__ int   g_cursor[MAXN];
__device__ int   g_blocksum[128];
__device__ int   g_bloff[128];
__device__ int2  g_edge[MAXE];
__device__ __align__(16) __half g_xh[(size_t)MAXN * 128];    // x in fp16
__device__ __align__(16) __half g_h1h[(size_t)MAXN * 256];   // h1 in fp16
__device__ __align__(16) __half g_a1h[(size_t)MAXN * 128];   // agg1 fp16
__device__ __align__(16) __half g_a2h[(size_t)MAXN * 256];   // agg2 fp16
__device__ __align__(16) __half g_h2h[(size_t)MAXN * 256];   // h2 fp16
__device__ __align__(16) __half g_b1hi[256 * 128];
__device__ __align__(16) __half g_b1lo[256 * 128];
__device__ __align__(16) __half g_b2hi[256 * 256];
__device__ __align__(16) __half g_b2lo[256 * 256];
__device__ float g_sums[NG * 256];
__device__ float g_cnt[NG];

// ---------------- prep kernels ----------------
__global__ void init_kernel(int n) {
    int i = blockIdx.x * blockDim.x + threadIdx.x;
    if (i < n) g_deg[i] = 0;
    if (i < NG * 256) g_sums[i] = 0.f;
    if (i < NG) g_cnt[i] = 0.f;
}

__global__ void deg_kernel(const int* __restrict__ ei, int E, int n) {
    int e = blockIdx.x * blockDim.x + threadIdx.x;
    if (e < E) {
        unsigned c = (unsigned)ei[E + e];
        if (c < (unsigned)n) atomicAdd(&g_deg[c], 1);
    }
}

__global__ void dinv_kernel(int n) {
    int i = blockIdx.x * blockDim.x + threadIdx.x;
    if (i < n) g_dinv[i] = rsqrtf((float)(g_deg[i] + 1));
}

// x fp32 -> fp16
__global__ void x_to_half(const float4* __restrict__ X, int total4) {
    int i = blockIdx.x * blockDim.x + threadIdx.x;
    if (i >= total4) return;
    float4 v = X[i];
    union { __half2 h[2]; uint2 u; } o;
    o.h[0] = __floats2half2_rn(v.x, v.y);
    o.h[1] = __floats2half2_rn(v.z, v.w);
    *(uint2*)(g_xh + (size_t)i * 4) = o.u;
}

// 3-phase multiblock scan
__global__ void scan1(int n) {
    __shared__ int wsum[32];
    int i = blockIdx.x * 1024 + threadIdx.x;
    int lane = threadIdx.x & 31, wid = threadIdx.x >> 5;
    int v = (i < n) ? g_deg[i] : 0;
    int s = v;
    #pragma unroll
    for (int off = 1; off < 32; off <<= 1) {
        int t = __shfl_up_sync(0xffffffffu, s, off);
        if (lane >= off) s += t;
    }
    if (lane == 31) wsum[wid] = s;
    __syncthreads();
    if (wid == 0) {
        int t = wsum[lane];
        int ss = t;
        #pragma unroll
        for (int off = 1; off < 32; off <<= 1) {
            int u = __shfl_up_sync(0xffffffffu, ss, off);
            if (lane >= off) ss += u;
        }
        wsum[lane] = ss - t;
    }
    __syncthreads();
    if (i < n) g_colptr[i] = wsum[wid] + s - v;
    if (threadIdx.x == 1023) g_blocksum[blockIdx.x] = wsum[31] + s;
}

__global__ void scan2(int nb, int n) {
    __shared__ int ws[4];
    int lane = threadIdx.x & 31, wid = threadIdx.x >> 5;
    int v = (threadIdx.x < nb) ? g_blocksum[threadIdx.x] : 0;
    int s = v;
    #pragma unroll
    for (int off = 1; off < 32; off <<= 1) {
        int t = __shfl_up_sync(0xffffffffu, s, off);
        if (lane >= off) s += t;
    }
    if (lane == 31) ws[wid] = s;
    __syncthreads();
    int base = 0;
    for (int w = 0; w < wid; w++) base += ws[w];
    int excl = base + s - v;
    if (threadIdx.x < nb) g_bloff[threadIdx.x] = excl;
    if (threadIdx.x == nb - 1) g_colptr[n] = excl + v;
}

__global__ void scan3(int n) {
    int i = blockIdx.x * blockDim.x + threadIdx.x;
    if (i < n) {
        int v = g_colptr[i] + g_bloff[i >> 10];
        g_colptr[i] = v;
        g_cursor[i] = v;
    }
}

__global__ void fill_kernel(const int* __restrict__ ei, int E, int n) {
    int e = blockIdx.x * blockDim.x + threadIdx.x;
    if (e >= E) return;
    unsigned r = (unsigned)ei[e];
    unsigned c = (unsigned)ei[E + e];
    if (r >= (unsigned)n || c >= (unsigned)n) return;
    int p = atomicAdd(&g_cursor[c], 1);
    g_edge[p] = make_int2((int)r, __float_as_int(g_dinv[r] * g_dinv[c]));
}

// transpose W [K,N] -> [N,K] with fp16 hi/lo split
__global__ void prep_weights(const float* __restrict__ W1, const float* __restrict__ W2) {
    int nn = blockIdx.x;
    for (int k = threadIdx.x; k < 128; k += 256) {
        float w = W1[k * 256 + nn];
        __half h = __float2half_rn(w);
        g_b1hi[nn * 128 + k] = h;
        g_b1lo[nn * 128 + k] = __float2half_rn(w - __half2float(h));
    }
    for (int k = threadIdx.x; k < 256; k += 256) {
        float w = W2[k * 256 + nn];
        __half h = __float2half_rn(w);
        g_b2hi[nn * 256 + k] = h;
        g_b2lo[nn * 256 + k] = __float2half_rn(w - __half2float(h));
    }
}

// ---------------- aggregation (CSR gather of fp16 rows, fp32 accumulate) --------
// Edge loop unrolled x4: batch edge reads then independent gathers -> MLP~4/warp.
__device__ __forceinline__ void fma_h4(float4& acc, uint2 u, float w) {
    union { __half2 h[2]; uint2 u2; } cv;
    cv.u2 = u;
    float2 f0 = __half22float2(cv.h[0]), f1 = __half22float2(cv.h[1]);
    acc.x = fmaf(f0.x, w, acc.x);
    acc.y = fmaf(f0.y, w, acc.y);
    acc.z = fmaf(f1.x, w, acc.z);
    acc.w = fmaf(f1.y, w, acc.w);
}
__device__ __forceinline__ void fma_h8(float* a, uint4 u, float w) {
    union { __half2 h[4]; uint4 u4; } cv;
    cv.u4 = u;
    float2 f0 = __half22float2(cv.h[0]), f1 = __half22float2(cv.h[1]);
    float2 f2 = __half22float2(cv.h[2]), f3 = __half22float2(cv.h[3]);
    a[0] = fmaf(f0.x, w, a[0]); a[1] = fmaf(f0.y, w, a[1]);
    a[2] = fmaf(f1.x, w, a[2]); a[3] = fmaf(f1.y, w, a[3]);
    a[4] = fmaf(f2.x, w, a[4]); a[5] = fmaf(f2.y, w, a[5]);
    a[6] = fmaf(f3.x, w, a[6]); a[7] = fmaf(f3.y, w, a[7]);
}

// layer 1, D=128: warp per node, lane owns 4 cols (uint2 = 8B)
__global__ void agg_d128(int n) {
    int node = blockIdx.x * 8 + (threadIdx.x >> 5);
    if (node >= n) return;
    int lane = threadIdx.x & 31;
    float di = g_dinv[node];
    float self = di * di;
    const uint2* Xh = (const uint2*)g_xh;
    union { __half2 h[2]; uint2 u; } cv;
    cv.u = Xh[(size_t)node * 32 + lane];
    float2 f0 = __half22float2(cv.h[0]), f1 = __half22float2(cv.h[1]);
    float4 acc = make_float4(f0.x * self, f0.y * self, f1.x * self, f1.y * self);
    int s = g_colptr[node], e = g_colptr[node + 1];
    int p = s;
    for (; p + 4 <= e; p += 4) {
        int2 e0 = g_edge[p], e1 = g_edge[p + 1], e2 = g_edge[p + 2], e3 = g_edge[p + 3];
        uint2 u0 = Xh[(size_t)e0.x * 32 + lane];
        uint2 u1 = Xh[(size_t)e1.x * 32 + lane];
        uint2 u2 = Xh[(size_t)e2.x * 32 + lane];
        uint2 u3 = Xh[(size_t)e3.x * 32 + lane];
        fma_h4(acc, u0, __int_as_float(e0.y));
        fma_h4(acc, u1, __int_as_float(e1.y));
        fma_h4(acc, u2, __int_as_float(e2.y));
        fma_h4(acc, u3, __int_as_float(e3.y));
    }
    for (; p < e; p++) {
        int2 ed = g_edge[p];
        fma_h4(acc, Xh[(size_t)ed.x * 32 + lane], __int_as_float(ed.y));
    }
    union { __half2 h[2]; uint2 u; } o;
    o.h[0] = __floats2half2_rn(acc.x, acc.y);
    o.h[1] = __floats2half2_rn(acc.z, acc.w);
    *(uint2*)(g_a1h + (size_t)node * 128 + lane * 4) = o.u;
}

// layer 2, D=256: warp per node, lane owns 8 cols (uint4 = 16B)
__global__ void agg_d256(int n) {
    int node = blockIdx.x * 8 + (threadIdx.x >> 5);
    if (node >= n) return;
    int lane = threadIdx.x & 31;
    const uint4* Xh = (const uint4*)g_h1h;
    float di = g_dinv[node];
    float self = di * di;
    union { __half2 h[4]; uint4 u; } cv;
    cv.u = Xh[(size_t)node * 32 + lane];
    float a[8];
    {
        float2 f0 = __half22float2(cv.h[0]), f1 = __half22float2(cv.h[1]);
        float2 f2 = __half22float2(cv.h[2]), f3 = __half22float2(cv.h[3]);
        a[0] = f0.x * self; a[1] = f0.y * self;
        a[2] = f1.x * self; a[3] = f1.y * self;
        a[4] = f2.x * self; a[5] = f2.y * self;
        a[6] = f3.x * self; a[7] = f3.y * self;
    }
    int s = g_colptr[node], e = g_colptr[node + 1];
    int p = s;
    for (; p + 4 <= e; p += 4) {
        int2 e0 = g_edge[p], e1 = g_edge[p + 1], e2 = g_edge[p + 2], e3 = g_edge[p + 3];
        uint4 u0 = Xh[(size_t)e0.x * 32 + lane];
        uint4 u1 = Xh[(size_t)e1.x * 32 + lane];
        uint4 u2 = Xh[(size_t)e2.x * 32 + lane];
        uint4 u3 = Xh[(size_t)e3.x * 32 + lane];
        fma_h8(a, u0, __int_as_float(e0.y));
        fma_h8(a, u1, __int_as_float(e1.y));
        fma_h8(a, u2, __int_as_float(e2.y));
        fma_h8(a, u3, __int_as_float(e3.y));
    }
    for (; p < e; p++) {
        int2 ed = g_edge[p];
        fma_h8(a, Xh[(size_t)ed.x * 32 + lane], __int_as_float(ed.y));
    }
    union { __half2 h[4]; uint4 u; } o;
    o.h[0] = __floats2half2_rn(a[0], a[1]);
    o.h[1] = __floats2half2_rn(a[2], a[3]);
    o.h[2] = __floats2half2_rn(a[4], a[5]);
    o.h[3] = __floats2half2_rn(a[6], a[7]);
    *(uint4*)(g_a2h + (size_t)node * 256 + lane * 8) = o.u;
}

// ---------------- HMMA fp16 (A single, W hi/lo) GEMM + bias + relu ----------------
// C[M,256] = A[M,K] @ W[K,256]. Block tile 128x128, 8 warps (4Mx2N), warp 32x64.
// Both layers write fp16.
template<int LAYER>
__global__ __launch_bounds__(256, 1) void gemm_mma(const float* __restrict__ bias, int M) {
    constexpr int K = (LAYER == 1) ? 128 : 256;
    constexpr int NCH = K / 32;
    const __half* A  = (LAYER == 1) ? g_a1h : g_a2h;
    const __half* WH = (LAYER == 1) ? g_b1hi : g_b2hi;
    const __half* WL = (LAYER == 1) ? g_b1lo : g_b2lo;
    __half* C = (LAYER == 1) ? g_h1h : g_h2h;

    __shared__ __align__(16) char smem[30720];
    uint32_t sb = smem_to_u32(smem);
    const uint32_t SA = 0, SH = 10240, SL = 20480;

    int tid = threadIdx.x, lane = tid & 31, wid = tid >> 5;
    int row0 = blockIdx.x * 128, col0 = blockIdx.y * 128;
    int wm = wid & 3, wn = wid >> 2;

    float acc[2][8][4];
    #pragma unroll
    for (int i = 0; i < 2; i++)
        #pragma unroll
        for (int j = 0; j < 8; j++)
            #pragma unroll
            for (int q = 0; q < 4; q++) acc[i][j][q] = 0.f;

    uint4 pA[2], pH[2], pL[2];
    auto prefetch = [&](int ch) {
        #pragma unroll
        for (int g = 0; g < 2; g++) {
            int idx = tid + g * 256;
            int r = idx >> 2, c = idx & 3;
            int gk = ch * 32 + c * 8;
            int ar = row0 + r;
            pA[g] = (ar < M) ? *(const uint4*)(A + (size_t)ar * K + gk)
                             : make_uint4(0, 0, 0, 0);
            int br = col0 + r;
            pH[g] = *(const uint4*)(WH + (size_t)br * K + gk);
            pL[g] = *(const uint4*)(WL + (size_t)br * K + gk);
        }
    };
    auto stage = [&]() {
        #pragma unroll
        for (int g = 0; g < 2; g++) {
            int idx = tid + g * 256;
            int r = idx >> 2, c = idx & 3;
            uint32_t o = (uint32_t)(r * 80 + c * 16);
            *(uint4*)(smem + SA + o) = pA[g];
            *(uint4*)(smem + SH + o) = pH[g];
            *(uint4*)(smem + SL + o) = pL[g];
        }
    };

    prefetch(0);
    stage();
    __syncthreads();

    for (int ch = 0; ch < NCH; ch++) {
        if (ch + 1 < NCH) prefetch(ch + 1);
        #pragma unroll
        for (int ks = 0; ks < 2; ks++) {
            int r = lane & 15;
            int kb = ks * 16 + ((lane >> 4) << 3);
            uint32_t a[2][4];
            #pragma unroll
            for (int mf = 0; mf < 2; mf++) {
                uint32_t off = (uint32_t)((wm * 32 + mf * 16 + r) * 80 + kb * 2);
                LDSM4(a[mf][0], a[mf][1], a[mf][2], a[mf][3], sb + SA + off);
            }
            uint32_t bH[8][2], bL[8][2];
            #pragma unroll
            for (int nq = 0; nq < 4; nq++) {
                uint32_t off = (uint32_t)((wn * 64 + nq * 16 + r) * 80 + kb * 2);
                uint32_t t0, t1, t2, t3;
                LDSM4(t0, t1, t2, t3, sb + SH + off);
                bH[nq * 2][0] = t0; bH[nq * 2][1] = t2;
                bH[nq * 2 + 1][0] = t1; bH[nq * 2 + 1][1] = t3;
                LDSM4(t0, t1, t2, t3, sb + SL + off);
                bL[nq * 2][0] = t0; bL[nq * 2][1] = t2;
                bL[nq * 2 + 1][0] = t1; bL[nq * 2 + 1][1] = t3;
            }
            #pragma unroll
            for (int mf = 0; mf < 2; mf++)
                #pragma unroll
                for (int nf = 0; nf < 8; nf++) {
                    MMA_F16(acc[mf][nf], a[mf], bH[nf]);
                    MMA_F16(acc[mf][nf], a[mf], bL[nf]);
                }
        }
        __syncthreads();
        if (ch + 1 < NCH) {
            stage();
            __syncthreads();
        }
    }

    // epilogue: fragment row = lane>>2 (+8), cols = (lane&3)*2..+1
    #pragma unroll
    for (int mf = 0; mf < 2; mf++)
        #pragma unroll
        for (int nf = 0; nf < 8; nf++) {
            int rr = row0 + wm * 32 + mf * 16 + (lane >> 2);
            int cc = col0 + wn * 64 + nf * 8 + (lane & 3) * 2;
            float bv0 = bias[cc], bv1 = bias[cc + 1];
            float v00 = fmaxf(acc[mf][nf][0] + bv0, 0.f);
            float v01 = fmaxf(acc[mf][nf][1] + bv1, 0.f);
            float v10 = fmaxf(acc[mf][nf][2] + bv0, 0.f);
            float v11 = fmaxf(acc[mf][nf][3] + bv1, 0.f);
            if (rr < M)
                *(__half2*)(C + (size_t)rr * 256 + cc) = __floats2half2_rn(v00, v01);
            if (rr + 8 < M)
                *(__half2*)(C + (size_t)(rr + 8) * 256 + cc) = __floats2half2_rn(v10, v11);
        }
}

// ---------------- pooling + final ----------------
__global__ void pool_kernel(const int* __restrict__ batch, int n) {
    int c = threadIdx.x;
    int start = blockIdx.x * 64;
    if (start >= n) return;
    int end = min(start + 64, n);
    float acc = 0.f;
    int g = batch[start] & (NG - 1);
    for (int i = start; i < end; i++) {
        int gi = batch[i] & (NG - 1);
        if (gi != g) {
            atomicAdd(&g_sums[g * 256 + c], acc);
            acc = 0.f;
            g = gi;
        }
        acc += __half2float(g_h2h[(size_t)i * 256 + c]);
    }
    atomicAdd(&g_sums[g * 256 + c], acc);
}

__global__ void count_kernel(const int* __restrict__ batch, int n) {
    int i = blockIdx.x * blockDim.x + threadIdx.x;
    if (i < n) atomicAdd(&g_cnt[batch[i] & (NG - 1)], 1.0f);
}

__global__ void final_kernel(const float* __restrict__ Wl,
                             const float* __restrict__ bl,
                             float* __restrict__ out) {
    int idx = threadIdx.x;
    int g = idx >> 1, c = idx & 1;
    float inv = 1.0f / fmaxf(g_cnt[g], 1.0f);
    float acc = bl[c];
    #pragma unroll 8
    for (int k = 0; k < 256; k++)
        acc = fmaf(g_sums[g * 256 + k] * inv, Wl[k * 2 + c], acc);
    out[idx] = acc;
}

// ---------------- launch ----------------
extern "C" void kernel_launch(void* const* d_in, const int* in_sizes, int n_in,
                              void* d_out, int out_size) {
    const float* x     = (const float*)d_in[0];
    const int*   ei    = (const int*)d_in[1];
    const int*   batch = (const int*)d_in[2];
    const float* W1    = (const float*)d_in[3];
    const float* b1    = (const float*)d_in[4];
    const float* W2    = (const float*)d_in[5];
    const float* b2    = (const float*)d_in[6];
    const float* Wl    = (const float*)d_in[7];
    const float* bl    = (const float*)d_in[8];
    float* out = (float*)d_out;

    int N = in_sizes[0] / 128;
    int E = in_sizes[1] / 2;
    int nb = (N + 1023) / 1024;

    // prep
    init_kernel<<<(N + 255) / 256, 256>>>(N);
    deg_kernel<<<(E + 255) / 256, 256>>>(ei, E, N);
    dinv_kernel<<<(N + 255) / 256, 256>>>(N);
    x_to_half<<<(N * 32 + 255) / 256, 256>>>((const float4*)x, N * 32);
    scan1<<<nb, 1024>>>(N);
    scan2<<<1, 128>>>(nb, N);
    scan3<<<(N + 255) / 256, 256>>>(N);
    prep_weights<<<256, 256>>>(W1, W2);
    fill_kernel<<<(E + 255) / 256, 256>>>(ei, E, N);

    int mtiles = (N + 127) / 128;
    dim3 ggrid(mtiles, 2);
    // layer 1
    agg_d128<<<(N + 7) / 8, 256>>>(N);
    gemm_mma<1><<<ggrid, 256>>>(b1, N);
    // layer 2
    agg_d256<<<(N + 7) / 8, 256>>>(N);
    gemm_mma<2><<<ggrid, 256>>>(b2, N);
    // pool + final
    pool_kernel<<<(N + 63) / 64, 256>>>(batch, N);
    count_kernel<<<(N + 255) / 256, 256>>>(batch, N);
    final_kernel<<<1, 128>>>(Wl, bl, out);
}